// round 16
// baseline (speedup 1.0000x reference)
#include <cuda_runtime.h>
#include <cuda_fp16.h>
#include <stdint.h>
#include <math.h>

#define NBATCH 8
#define NPIX   4096
#define DEMB   128
#define ATT_SCALE 0.08838834764831845f
#define LOG2E 1.4426950408889634f
#define BN_EPS 1e-5f

// fp16 planes for attention operands: (dir*3+kind), kind 0 Q,1 K,2 V.
// Q,K stored [n][d]; V stored [d][n]. Q pre-scaled by ATT_SCALE*LOG2E.
__device__ __half g_h[(size_t)6 * NBATCH * DEMB * NPIX];        // 50 MB
// input features fp16, layout [input][b][k=256][n=4096]
__device__ __half g_x[(size_t)2 * NBATCH * 256 * NPIX];         // 16.8 MB
// attention output (concat) fp16 [b][256][4096]
__device__ __half g_ch[(size_t)NBATCH * 256 * NPIX];            // 16.8 MB
// weights fp16: 6 proj W [128][256] at p*32768, then w_proj [256][256] at 196608
__device__ __half g_w[262144];

// ------------------------------------------------------------- helpers -----
__device__ __forceinline__ uint32_t smem_u32(const void* p) {
    uint32_t a;
    asm("{ .reg .u64 t; cvta.to.shared.u64 t, %1; cvt.u32.u64 %0, t; }" : "=r"(a) : "l"(p));
    return a;
}
__device__ __forceinline__ uint32_t pkh(float a, float b) {
    __half2 h = __floats2half2_rn(a, b);
    return *reinterpret_cast<uint32_t*>(&h);
}
__device__ __forceinline__ float ex2(float x) {
    float r;
    asm("ex2.approx.ftz.f32 %0, %1;" : "=f"(r) : "f"(x));
    return r;
}
__device__ __forceinline__ void mma_f16(float c[4], const uint32_t a[4],
                                        uint32_t b0, uint32_t b1) {
    asm volatile("mma.sync.aligned.m16n8k16.row.col.f32.f16.f16.f32 "
        "{%0,%1,%2,%3}, {%4,%5,%6,%7}, {%8,%9}, {%0,%1,%2,%3};"
        : "+f"(c[0]), "+f"(c[1]), "+f"(c[2]), "+f"(c[3])
        : "r"(a[0]), "r"(a[1]), "r"(a[2]), "r"(a[3]), "r"(b0), "r"(b1));
}
// f16-accumulate variant: C/D are 2 regs of f16x2 (row-lo pair, row-hi pair)
__device__ __forceinline__ void mma_f16h(uint32_t c[2], const uint32_t a[4],
                                         uint32_t b0, uint32_t b1) {
    asm volatile("mma.sync.aligned.m16n8k16.row.col.f16.f16.f16.f16 "
        "{%0,%1}, {%2,%3,%4,%5}, {%6,%7}, {%0,%1};"
        : "+r"(c[0]), "+r"(c[1])
        : "r"(a[0]), "r"(a[1]), "r"(a[2]), "r"(a[3]), "r"(b0), "r"(b1));
}
__device__ __forceinline__ void ldsm4(uint32_t r[4], uint32_t addr) {
    asm volatile("ldmatrix.sync.aligned.m8n8.x4.shared.b16 {%0,%1,%2,%3}, [%4];"
        : "=r"(r[0]), "=r"(r[1]), "=r"(r[2]), "=r"(r[3]) : "r"(addr));
}
__device__ __forceinline__ void ldsm4t(uint32_t r[4], uint32_t addr) {
    asm volatile("ldmatrix.sync.aligned.m8n8.x4.trans.shared.b16 {%0,%1,%2,%3}, [%4];"
        : "=r"(r[0]), "=r"(r[1]), "=r"(r[2]), "=r"(r[3]) : "r"(addr));
}
__device__ __forceinline__ void cpa16(uint32_t s, const void* g) {
    asm volatile("cp.async.cg.shared.global [%0], [%1], 16;" :: "r"(s), "l"(g));
}
#define CP_COMMIT() asm volatile("cp.async.commit_group;" ::: "memory")
#define CP_WAIT(n)  asm volatile("cp.async.wait_group %0;" :: "n"(n) : "memory")

// ---------------- merged fp32 -> fp16 converter -----------------------------
struct CvtTab {
    const float* src[9];
    __half* dst[9];
    int blkoff[10];     // block-index prefix (2048 elems per block)
};

__global__ __launch_bounds__(256) void cvt_all(CvtTab t)
{
    int blk = blockIdx.x, seg = 0;
    while (blk >= t.blkoff[seg + 1]) seg++;
    int i = ((blk - t.blkoff[seg]) * 256 + threadIdx.x) * 8;
    const float* src = t.src[seg];
    __half* dst = t.dst[seg];

    float4 a = *(const float4*)(src + i);
    float4 b = *(const float4*)(src + i + 4);
    uint2 o0 = make_uint2(pkh(a.x, a.y), pkh(a.z, a.w));
    uint2 o1 = make_uint2(pkh(b.x, b.y), pkh(b.z, b.w));
    *(uint2*)(dst + i) = o0;
    *(uint2*)(dst + i + 4) = o1;
}

// ---------------- 1-term fp16 GEMM constants (K-chunk 64) -------------------
#define FB_XH 0
#define FB_WH 17408
#define FB_BUF 35840
#define GEMM_SMEM 71680

struct ProjTab {
    int woff[6];
    const float* bias[6];
    float scale[6];
    int vmode[6];           // 0: out [n][d], 1: out [d][n]
    __half* out[6];
};

// proj: Y(128, 4096-tile) = W(128,256) @ X(256,4096) + bias, fp16 out planes
__global__ __launch_bounds__(256, 2) void proj_mma(ProjTab pt)
{
    extern __shared__ char sm[];
    const int tid = threadIdx.x, lane = tid & 31, w = tid >> 5;
    const int nb = blockIdx.x * 128;
    const int input = blockIdx.z >> 3, b = blockIdx.z & 7;
    const int p = input * 3 + blockIdx.y;

    const __half* Xh = g_x + (size_t)(input * 8 + b) * 256 * NPIX;
    const __half* Wh = g_w + pt.woff[p];
    const float* bias = pt.bias[p];
    const float scale = pt.scale[p];
    const int vmode = pt.vmode[p];
    __half* out = pt.out[p] + (size_t)b * DEMB * NPIX;

    const uint32_t sb = smem_u32(sm);

    auto fill = [&](int c, int s) {
        uint32_t base = sb + s * FB_BUF;
#pragma unroll
        for (int i = 0; i < 4; i++) {   // X: 64 rows x 16 chunks
            int idx = tid + 256 * i, r = idx >> 4, ch = idx & 15;
            cpa16(base + FB_XH + r * 272 + ch * 16,
                  Xh + (size_t)(c * 64 + r) * NPIX + nb + ch * 8);
        }
#pragma unroll
        for (int i = 0; i < 4; i++) {   // W: 128 rows x 8 chunks
            int idx = tid + 256 * i, m = idx >> 3, ch = idx & 7;
            cpa16(base + FB_WH + m * 144 + ch * 16,
                  Wh + (size_t)m * 256 + c * 64 + ch * 8);
        }
    };

    fill(0, 0); CP_COMMIT();
    fill(1, 1); CP_COMMIT();

    const int lr = lane & 7, g = lane >> 3;
    const int fr = lr + ((g & 1) << 3), fc = g >> 1;
    const int wm = w >> 2, wn = w & 3;

    float C[4][4][4];
#pragma unroll
    for (int i = 0; i < 4; i++)
#pragma unroll
        for (int j = 0; j < 4; j++)
#pragma unroll
            for (int k = 0; k < 4; k++) C[i][j][k] = 0.f;

    for (int c = 0; c < 4; c++) {
        if (c < 2) { CP_WAIT(1); } else { CP_WAIT(0); }
        __syncthreads();
        const uint32_t base = sb + (c & 1) * FB_BUF;
#pragma unroll
        for (int kt = 0; kt < 4; kt++) {
            uint32_t bh[2][4];
#pragma unroll
            for (int nh = 0; nh < 2; nh++)
                ldsm4t(bh[nh], base + FB_XH + (kt * 16 + fr) * 272 +
                               (wn * 32 + nh * 16 + fc * 8) * 2);
#pragma unroll
            for (int mt = 0; mt < 4; mt++) {
                uint32_t ah[4];
                ldsm4(ah, base + FB_WH + (wm * 64 + mt * 16 + fr) * 144 +
                          (kt * 16 + fc * 8) * 2);
#pragma unroll
                for (int nh = 0; nh < 2; nh++) {
                    mma_f16(C[mt][2 * nh], ah, bh[nh][0], bh[nh][1]);
                    mma_f16(C[mt][2 * nh + 1], ah, bh[nh][2], bh[nh][3]);
                }
            }
        }
        __syncthreads();
        if (c + 2 < 4) { fill(c + 2, c & 1); CP_COMMIT(); }
    }

    // epilogue: bias+scale, fp16, stage to target layout (pitch 272B)
    __half* stage = (__half*)sm;
#pragma unroll
    for (int mt = 0; mt < 4; mt++) {
        int m0 = wm * 64 + mt * 16 + (lane >> 2);
        float b0 = bias[m0], b1 = bias[m0 + 8];
#pragma unroll
        for (int nt = 0; nt < 4; nt++) {
            int n = wn * 32 + nt * 8 + 2 * (lane & 3);
            float v0 = (C[mt][nt][0] + b0) * scale;
            float v1 = (C[mt][nt][1] + b0) * scale;
            float v2 = (C[mt][nt][2] + b1) * scale;
            float v3 = (C[mt][nt][3] + b1) * scale;
            if (vmode == 0) {   // stage [n][d]
                stage[n * 136 + m0] = __float2half_rn(v0);
                stage[(n + 1) * 136 + m0] = __float2half_rn(v1);
                stage[n * 136 + m0 + 8] = __float2half_rn(v2);
                stage[(n + 1) * 136 + m0 + 8] = __float2half_rn(v3);
            } else {            // stage [d][n]
                *(uint32_t*)&stage[m0 * 136 + n] = pkh(v0, v1);
                *(uint32_t*)&stage[(m0 + 8) * 136 + n] = pkh(v2, v3);
            }
        }
    }
    __syncthreads();
#pragma unroll
    for (int i = 0; i < 8; i++) {
        int idx = tid + 256 * i, r = idx >> 4, ch = idx & 15;
        uint4 v = *(uint4*)((char*)sm + r * 272 + ch * 16);
        if (vmode == 0)
            *(uint4*)(out + (size_t)(nb + r) * DEMB + ch * 8) = v;
        else
            *(uint4*)(out + (size_t)r * NPIX + nb + ch * 8) = v;
    }
}

// ---------------- final GEMM (1-term fp16, K-chunk 64) ----------------------
#define FINAL_SMEM 71680

__global__ __launch_bounds__(256, 2) void final_mma(
    float* __restrict__ Y,
    const float* __restrict__ bng, const float* __restrict__ bnb,
    const float* __restrict__ bnm, const float* __restrict__ bnv)
{
    extern __shared__ char sm[];
    const int tid = threadIdx.x, lane = tid & 31, w = tid >> 5;
    const int nb = blockIdx.x * 128;
    const int mbase = blockIdx.y * 128;
    const int b = blockIdx.z;

    const __half* Xh = g_ch + (size_t)b * 256 * NPIX;
    const __half* Wh = g_w + 196608;
    float* Yb = Y + (size_t)b * 256 * NPIX;

    const uint32_t sb = smem_u32(sm);

    auto fill = [&](int c, int s) {
        uint32_t base = sb + s * FB_BUF;
#pragma unroll
        for (int i = 0; i < 4; i++) {
            int idx = tid + 256 * i, r = idx >> 4, ch = idx & 15;
            cpa16(base + FB_XH + r * 272 + ch * 16,
                  Xh + (size_t)(c * 64 + r) * NPIX + nb + ch * 8);
        }
#pragma unroll
        for (int i = 0; i < 4; i++) {
            int idx = tid + 256 * i, m = idx >> 3, ch = idx & 7;
            cpa16(base + FB_WH + m * 144 + ch * 16,
                  Wh + (size_t)(mbase + m) * 256 + c * 64 + ch * 8);
        }
    };

    fill(0, 0); CP_COMMIT();
    fill(1, 1); CP_COMMIT();

    const int lr = lane & 7, g = lane >> 3;
    const int fr = lr + ((g & 1) << 3), fc = g >> 1;
    const int wm = w >> 2, wn = w & 3;

    float C[4][4][4];
#pragma unroll
    for (int i = 0; i < 4; i++)
#pragma unroll
        for (int j = 0; j < 4; j++)
#pragma unroll
            for (int k = 0; k < 4; k++) C[i][j][k] = 0.f;

    for (int c = 0; c < 4; c++) {
        if (c < 2) { CP_WAIT(1); } else { CP_WAIT(0); }
        __syncthreads();
        const uint32_t base = sb + (c & 1) * FB_BUF;
#pragma unroll
        for (int kt = 0; kt < 4; kt++) {
            uint32_t bh[2][4];
#pragma unroll
            for (int nh = 0; nh < 2; nh++)
                ldsm4t(bh[nh], base + FB_XH + (kt * 16 + fr) * 272 +
                               (wn * 32 + nh * 16 + fc * 8) * 2);
#pragma unroll
            for (int mt = 0; mt < 4; mt++) {
                uint32_t ah[4];
                ldsm4(ah, base + FB_WH + (wm * 64 + mt * 16 + fr) * 144 +
                          (kt * 16 + fc * 8) * 2);
#pragma unroll
                for (int nh = 0; nh < 2; nh++) {
                    mma_f16(C[mt][2 * nh], ah, bh[nh][0], bh[nh][1]);
                    mma_f16(C[mt][2 * nh + 1], ah, bh[nh][2], bh[nh][3]);
                }
            }
        }
        __syncthreads();
        if (c + 2 < 4) { fill(c + 2, c & 1); CP_COMMIT(); }
    }

    // BN + ReLU, stage fp32 [m][n] pitch 132 floats, coalesced STG
    float* stage = (float*)sm;
#pragma unroll
    for (int mt = 0; mt < 4; mt++) {
        int ml = wm * 64 + mt * 16 + (lane >> 2);
        int m0 = mbase + ml, m1 = m0 + 8;
        float i0 = bng[m0] * rsqrtf(bnv[m0] + BN_EPS);
        float s0 = bnb[m0] - bnm[m0] * i0;
        float i1 = bng[m1] * rsqrtf(bnv[m1] + BN_EPS);
        float s1 = bnb[m1] - bnm[m1] * i1;
#pragma unroll
        for (int nt = 0; nt < 4; nt++) {
            int n = wn * 32 + nt * 8 + 2 * (lane & 3);
            stage[ml * 132 + n]       = fmaxf(fmaf(C[mt][nt][0], i0, s0), 0.f);
            stage[ml * 132 + n + 1]   = fmaxf(fmaf(C[mt][nt][1], i0, s0), 0.f);
            stage[(ml + 8) * 132 + n]     = fmaxf(fmaf(C[mt][nt][2], i1, s1), 0.f);
            stage[(ml + 8) * 132 + n + 1] = fmaxf(fmaf(C[mt][nt][3], i1, s1), 0.f);
        }
    }
    __syncthreads();
#pragma unroll
    for (int i = 0; i < 16; i++) {
        int idx = tid + 256 * i, r = idx >> 5, ch = idx & 31;
        float4 v = *(float4*)((char*)sm + r * 528 + ch * 16);
        *(float4*)&Yb[(size_t)(mbase + r) * NPIX + nb + ch * 4] = v;
    }
}

// ---------------- flash attention: BQ=64, BK=128, f16-acc QK^T --------------
// warps: slab = w&3 (16-q slab), khalf = w>>2 (64-key half of each 128-key tile)
// smem: Q 16KB | K0 K1 V0 V1 32KB each = 144KB; 1 CTA/SM, grid 1024 (~7 waves)
#define ATT_SMEM (16384 + 4 * 32768)

__global__ __launch_bounds__(256, 1) void attn_kernel()
{
    extern __shared__ char sm[];
    const int tid = threadIdx.x, lane = tid & 31, w = tid >> 5;
    const int slab = w & 3, khalf = w >> 2;
    const int qt = blockIdx.x, dir = blockIdx.y, b = blockIdx.z;
    const int qbase = qt * 64;
    const size_t PLANE = (size_t)DEMB * NPIX;

    const __half* Qg = g_h + ((size_t)(dir * 3 + 0) * NBATCH + b) * PLANE;
    const __half* Kg = g_h + ((size_t)(dir * 3 + 1) * NBATCH + b) * PLANE;
    const __half* Vg = g_h + ((size_t)(dir * 3 + 2) * NBATCH + b) * PLANE;
    __half* Oh = g_ch + ((size_t)b * 256 + dir * 128) * NPIX;

    const uint32_t bQ = smem_u32(sm);
    const uint32_t bK0 = bQ + 16384, bK1 = bQ + 49152;
    const uint32_t bV0 = bQ + 81920, bV1 = bQ + 114688;

    auto fillA = [&](uint32_t dst, const __half* src, int rstride) {
#pragma unroll
        for (int i = 0; i < 8; i++) {
            int idx = tid + 256 * i;
            int r = idx >> 4, c = idx & 15;
            int ch = (c & 8) | ((c & 7) ^ (r & 7));
            cpa16(dst + r * 256 + ch * 16, src + (size_t)r * rstride + c * 8);
        }
    };
    auto fillQ = [&]() {
#pragma unroll
        for (int i = 0; i < 4; i++) {
            int idx = tid + 256 * i;
            int r = idx >> 4, c = idx & 15;
            int ch = (c & 8) | ((c & 7) ^ (r & 7));
            cpa16(bQ + r * 256 + ch * 16, Qg + (size_t)(qbase + r) * DEMB + c * 8);
        }
    };

    fillQ();                                              CP_COMMIT();
    fillA(bK0, Kg, DEMB); fillA(bV0, Vg, NPIX);           CP_COMMIT();
    fillA(bK1, Kg + (size_t)128 * DEMB, DEMB);
    fillA(bV1, Vg + 128, NPIX);                           CP_COMMIT();

    const int lr = lane & 7, g = lane >> 3;
    const int a_row = lr + ((g & 1) << 3), a_ch = g >> 1;
    const int b_row = lr + ((g >> 1) << 3), b_ch = g & 1;
    const int q0 = 16 * slab;

    CP_WAIT(2);
    __syncthreads();

    uint32_t qf[8][4];
#pragma unroll
    for (int k = 0; k < 8; k++) {
        int ch = 2 * k + a_ch;
        ldsm4(qf[k], bQ + (q0 + a_row) * 256 + (((ch & 8) | ((ch & 7) ^ lr)) << 4));
    }

    float O[16][4];
#pragma unroll
    for (int i = 0; i < 16; i++)
#pragma unroll
        for (int j = 0; j < 4; j++) O[i][j] = 0.f;
    float l0 = 0.f, l1 = 0.f;

    for (int t = 0; t < 32; t++) {
        if (t < 30) { CP_WAIT(1); } else { CP_WAIT(0); }
        __syncthreads();
        const uint32_t bK = (t & 1) ? bK1 : bK0;
        const uint32_t bV = (t & 1) ? bV1 : bV0;

        // ---- S (16q x 64 keys), f16 accumulate: Sh[i][0]=row-lo h2, [1]=row-hi
        uint32_t Sh[8][2];
#pragma unroll
        for (int i = 0; i < 8; i++) { Sh[i][0] = 0u; Sh[i][1] = 0u; }
#pragma unroll
        for (int d = 0; d < 8; d++) {
            int ch = 2 * d + b_ch;
            uint32_t co = ((ch & 8) | ((ch & 7) ^ lr)) << 4;
#pragma unroll
            for (int kc = 0; kc < 4; kc++) {
                uint32_t bk[4];
                ldsm4(bk, bK + ((khalf * 4 + kc) * 16 + b_row) * 256 + co);
                mma_f16h(Sh[2 * kc], qf[d], bk[0], bk[1]);
                mma_f16h(Sh[2 * kc + 1], qf[d], bk[2], bk[3]);
            }
        }

        // ---- softmax: unpack f16 scores, MUFU ex2 (Q pre-scaled by log2e) ----
        uint32_t ph[4][4];
#pragma unroll
        for (int kc = 0; kc < 4; kc++) {
            float2 a0 = __half22float2(*(__half2*)&Sh[2 * kc][0]);      // row-lo c0,c1
            float2 a1 = __half22float2(*(__half2*)&Sh[2 * kc][1]);      // row-hi c0,c1
            float2 b0 = __half22float2(*(__half2*)&Sh[2 * kc + 1][0]);  // row-lo c2,c3
            float2 b1 = __half22float2(*(__half2*)&Sh[2 * kc + 1][1]);  // row-hi c2,c3
            float e00 = ex2(a0.x), e01 = ex2(a0.y);
            float e02 = ex2(a1.x), e03 = ex2(a1.y);
            float e10 = ex2(b0.x), e11 = ex2(b0.y);
            float e12 = ex2(b1.x), e13 = ex2(b1.y);
            l0 += e00 + e01 + e10 + e11;
            l1 += e02 + e03 + e12 + e13;
            ph[kc][0] = pkh(e00, e01); ph[kc][1] = pkh(e02, e03);
            ph[kc][2] = pkh(e10, e11); ph[kc][3] = pkh(e12, e13);
        }

        // ---- O += P V over this key half (f32 acc): kc-outer, nb-inner ----
#pragma unroll
        for (int kc = 0; kc < 4; kc++) {
            int ch = 2 * (khalf * 4 + kc) + b_ch;
            uint32_t co = ((ch & 8) | ((ch & 7) ^ lr)) << 4;
#pragma unroll
            for (int nb2 = 0; nb2 < 8; nb2++) {
                uint32_t bv[4];
                ldsm4(bv, bV + (nb2 * 16 + b_row) * 256 + co);
                mma_f16(O[2 * nb2], ph[kc], bv[0], bv[1]);
                mma_f16(O[2 * nb2 + 1], ph[kc], bv[2], bv[3]);
            }
        }
        __syncthreads();
        if (t + 2 < 32) {
            fillA((t & 1) ? bK1 : bK0, Kg + (size_t)(t + 2) * 128 * DEMB, DEMB);
            fillA((t & 1) ? bV1 : bV0, Vg + (t + 2) * 128, NPIX);
            CP_COMMIT();
        }
    }

    // quad-reduce l over the 16-key column groups this warp saw
#pragma unroll
    for (int off = 1; off < 4; off <<= 1) {
        l0 += __shfl_xor_sync(0xffffffffu, l0, off);
        l1 += __shfl_xor_sync(0xffffffffu, l1, off);
    }

    // cross-warp (key-half) reduce through smem, then store
    float* sO = (float*)(sm + 16384);          // 64 rows x pitch 132 fp32
    float* sL = (float*)(sm + 16384 + 34048);  // 64 floats
    const int row0 = slab * 16 + (lane >> 2);
    __syncthreads();
    if (khalf == 1) {
        if ((lane & 3) == 0) { sL[row0] = l0; sL[row0 + 8] = l1; }
#pragma unroll
        for (int nb2 = 0; nb2 < 16; nb2++) {
            int d = nb2 * 8 + 2 * (lane & 3);
            sO[row0 * 132 + d] = O[nb2][0];
            sO[row0 * 132 + d + 1] = O[nb2][1];
            sO[(row0 + 8) * 132 + d] = O[nb2][2];
            sO[(row0 + 8) * 132 + d + 1] = O[nb2][3];
        }
    }
    __syncthreads();
    if (khalf == 0) {
        l0 += sL[row0];
        l1 += sL[row0 + 8];
        const float inv0 = 1.f / l0, inv1 = 1.f / l1;
        const int qg0 = qbase + row0;
#pragma unroll
        for (int nb2 = 0; nb2 < 16; nb2++) {
            int d = nb2 * 8 + 2 * (lane & 3);
            float v0 = (O[nb2][0] + sO[row0 * 132 + d]) * inv0;
            float v1 = (O[nb2][1] + sO[row0 * 132 + d + 1]) * inv0;
            float v2 = (O[nb2][2] + sO[(row0 + 8) * 132 + d]) * inv1;
            float v3 = (O[nb2][3] + sO[(row0 + 8) * 132 + d + 1]) * inv1;
            Oh[(size_t)d * NPIX + qg0]           = __float2half_rn(v0);
            Oh[(size_t)(d + 1) * NPIX + qg0]     = __float2half_rn(v1);
            Oh[(size_t)d * NPIX + qg0 + 8]       = __float2half_rn(v2);
            Oh[(size_t)(d + 1) * NPIX + qg0 + 8] = __float2half_rn(v3);
        }
    }
}

// ---------------- launch -----------------------------------------------------
extern "C" void kernel_launch(void* const* d_in, const int* in_sizes, int n_in,
                              void* d_out, int out_size)
{
    (void)in_sizes; (void)n_in; (void)out_size;
    const float* f_rgb   = (const float*)d_in[0];
    const float* f_pl    = (const float*)d_in[1];
    const float* w_q_rgb = (const float*)d_in[2];
    const float* b_q_rgb = (const float*)d_in[3];
    const float* w_k_pl  = (const float*)d_in[4];
    const float* b_k_pl  = (const float*)d_in[5];
    const float* w_v_pl  = (const float*)d_in[6];
    const float* b_v_pl  = (const float*)d_in[7];
    const float* w_q_pl  = (const float*)d_in[8];
    const float* b_q_pl  = (const float*)d_in[9];
    const float* w_k_rgb = (const float*)d_in[10];
    const float* b_k_rgb = (const float*)d_in[11];
    const float* w_v_rgb = (const float*)d_in[12];
    const float* b_v_rgb = (const float*)d_in[13];
    const float* w_proj  = (const float*)d_in[14];
    const float* bn_g    = (const float*)d_in[15];
    const float* bn_b    = (const float*)d_in[16];
    const float* bn_m    = (const float*)d_in[17];
    const float* bn_v    = (const float*)d_in[18];

    __half *hp, *xp, *wp;
    cudaGetSymbolAddress((void**)&hp, g_h);
    cudaGetSymbolAddress((void**)&xp, g_x);
    cudaGetSymbolAddress((void**)&wp, g_w);

    const int NX = NBATCH * 256 * NPIX;
    CvtTab ct;
    const float* srcs[9] = { f_rgb, f_pl, w_q_rgb, w_k_rgb, w_v_rgb,
                             w_k_pl, w_v_pl, w_q_pl, w_proj };
    int sizes[9] = { NX, NX, 32768, 32768, 32768, 32768, 32768, 32768, 65536 };
    __half* dsts[9] = { xp, xp + NX, wp, wp + 32768, wp + 65536,
                        wp + 98304, wp + 131072, wp + 163840, wp + 196608 };
    int off = 0;
    for (int i = 0; i < 9; i++) {
        ct.src[i] = srcs[i]; ct.dst[i] = dsts[i];
        ct.blkoff[i] = off;
        off += sizes[i] / 2048;
    }
    ct.blkoff[9] = off;
    cvt_all<<<off, 256>>>(ct);

    const size_t PL = (size_t)NBATCH * DEMB * NPIX;
    ProjTab pt;
    int woffs[6] = { 0, 32768, 65536, 98304, 131072, 163840 };
    const float* biases[6] = { b_q_rgb, b_k_rgb, b_v_rgb, b_k_pl, b_v_pl, b_q_pl };
    float scales[6] = { ATT_SCALE * LOG2E, 1.f, 1.f, 1.f, 1.f, ATT_SCALE * LOG2E };
    int vmodes[6] = { 0, 0, 1, 0, 1, 0 };
    int planes[6] = { 0, 4, 5, 1, 2, 3 };  // Qa, Kb, Vb, Ka, Va, Qb
    for (int i = 0; i < 6; i++) {
        pt.woff[i] = woffs[i]; pt.bias[i] = biases[i];
        pt.scale[i] = scales[i]; pt.vmode[i] = vmodes[i];
        pt.out[i] = hp + (size_t)planes[i] * PL;
    }

    cudaFuncSetAttribute(proj_mma, cudaFuncAttributeMaxDynamicSharedMemorySize, GEMM_SMEM);
    proj_mma<<<dim3(32, 3, 16), 256, GEMM_SMEM>>>(pt);

    cudaFuncSetAttribute(attn_kernel, cudaFuncAttributeMaxDynamicSharedMemorySize, ATT_SMEM);
    attn_kernel<<<dim3(NPIX / 64, 2, NBATCH), 256, ATT_SMEM>>>();

    cudaFuncSetAttribute(final_mma, cudaFuncAttributeMaxDynamicSharedMemorySize, FINAL_SMEM);
    final_mma<<<dim3(32, 2, NBATCH), 256, FINAL_SMEM>>>((float*)d_out,
                                                        bn_g, bn_b, bn_m, bn_v);
}

// round 17
// speedup vs baseline: 1.0136x; 1.0136x over previous
#include <cuda_runtime.h>
#include <cuda_fp16.h>
#include <stdint.h>
#include <math.h>

#define NBATCH 8
#define NPIX   4096
#define DEMB   128
#define ATT_SCALE 0.08838834764831845f
#define LOG2E 1.4426950408889634f
#define BN_EPS 1e-5f

// fp16 planes for attention operands: (dir*3+kind), kind 0 Q,1 K,2 V.
// Q,K stored [n][d]; V stored [d][n]. Q pre-scaled by ATT_SCALE*LOG2E.
__device__ __half g_h[(size_t)6 * NBATCH * DEMB * NPIX];        // 50 MB
// input features fp16, layout [input][b][k=256][n=4096]
__device__ __half g_x[(size_t)2 * NBATCH * 256 * NPIX];         // 16.8 MB
// attention output (concat) fp16 [b][256][4096]
__device__ __half g_ch[(size_t)NBATCH * 256 * NPIX];            // 16.8 MB
// weights fp16: 6 proj W [128][256] at p*32768, then w_proj [256][256] at 196608
__device__ __half g_w[262144];

// ------------------------------------------------------------- helpers -----
__device__ __forceinline__ uint32_t smem_u32(const void* p) {
    uint32_t a;
    asm("{ .reg .u64 t; cvta.to.shared.u64 t, %1; cvt.u32.u64 %0, t; }" : "=r"(a) : "l"(p));
    return a;
}
__device__ __forceinline__ uint32_t pkh(float a, float b) {
    __half2 h = __floats2half2_rn(a, b);
    return *reinterpret_cast<uint32_t*>(&h);
}
__device__ __forceinline__ float ex2(float x) {
    float r;
    asm("ex2.approx.ftz.f32 %0, %1;" : "=f"(r) : "f"(x));
    return r;
}
__device__ __forceinline__ void mma_f16(float c[4], const uint32_t a[4],
                                        uint32_t b0, uint32_t b1) {
    asm volatile("mma.sync.aligned.m16n8k16.row.col.f32.f16.f16.f32 "
        "{%0,%1,%2,%3}, {%4,%5,%6,%7}, {%8,%9}, {%0,%1,%2,%3};"
        : "+f"(c[0]), "+f"(c[1]), "+f"(c[2]), "+f"(c[3])
        : "r"(a[0]), "r"(a[1]), "r"(a[2]), "r"(a[3]), "r"(b0), "r"(b1));
}
__device__ __forceinline__ void ldsm4(uint32_t r[4], uint32_t addr) {
    asm volatile("ldmatrix.sync.aligned.m8n8.x4.shared.b16 {%0,%1,%2,%3}, [%4];"
        : "=r"(r[0]), "=r"(r[1]), "=r"(r[2]), "=r"(r[3]) : "r"(addr));
}
__device__ __forceinline__ void ldsm4t(uint32_t r[4], uint32_t addr) {
    asm volatile("ldmatrix.sync.aligned.m8n8.x4.trans.shared.b16 {%0,%1,%2,%3}, [%4];"
        : "=r"(r[0]), "=r"(r[1]), "=r"(r[2]), "=r"(r[3]) : "r"(addr));
}
__device__ __forceinline__ void cpa16(uint32_t s, const void* g) {
    asm volatile("cp.async.cg.shared.global [%0], [%1], 16;" :: "r"(s), "l"(g));
}
#define CP_COMMIT() asm volatile("cp.async.commit_group;" ::: "memory")
#define CP_WAIT(n)  asm volatile("cp.async.wait_group %0;" :: "n"(n) : "memory")

// ---------------- merged fp32 -> fp16 converter -----------------------------
struct CvtTab {
    const float* src[9];
    __half* dst[9];
    int blkoff[10];     // block-index prefix (2048 elems per block)
};

__global__ __launch_bounds__(256) void cvt_all(CvtTab t)
{
    int blk = blockIdx.x, seg = 0;
    while (blk >= t.blkoff[seg + 1]) seg++;
    int i = ((blk - t.blkoff[seg]) * 256 + threadIdx.x) * 8;
    const float* src = t.src[seg];
    __half* dst = t.dst[seg];

    float4 a = *(const float4*)(src + i);
    float4 b = *(const float4*)(src + i + 4);
    uint2 o0 = make_uint2(pkh(a.x, a.y), pkh(a.z, a.w));
    uint2 o1 = make_uint2(pkh(b.x, b.y), pkh(b.z, b.w));
    *(uint2*)(dst + i) = o0;
    *(uint2*)(dst + i + 4) = o1;
}

// ---------------- 1-term fp16 GEMM constants (K-chunk 32) -------------------
#define FB_XH 0
#define FB_WH 8704
#define FB_BUF 18944
#define GEMM_SMEM 37888     // 2 bufs; epilogue stage (<=34816B) reuses them

struct ProjTab {
    int woff[6];
    const float* bias[6];
    float scale[6];
    int vmode[6];           // 0: out [n][d], 1: out [d][n]
    __half* out[6];
};

// proj: Y(128, 4096-tile) = W(128,256) @ X(256,4096) + bias, fp16 out planes
__global__ __launch_bounds__(256, 2) void proj_mma(ProjTab pt)
{
    extern __shared__ char sm[];
    const int tid = threadIdx.x, lane = tid & 31, w = tid >> 5;
    const int nb = blockIdx.x * 128;
    const int input = blockIdx.z >> 3, b = blockIdx.z & 7;
    const int p = input * 3 + blockIdx.y;

    const __half* Xh = g_x + (size_t)(input * 8 + b) * 256 * NPIX;
    const __half* Wh = g_w + pt.woff[p];
    const float* bias = pt.bias[p];
    const float scale = pt.scale[p];
    const int vmode = pt.vmode[p];
    __half* out = pt.out[p] + (size_t)b * DEMB * NPIX;

    const uint32_t sb = smem_u32(sm);

    auto fill = [&](int c, int s) {
        uint32_t base = sb + s * FB_BUF;
#pragma unroll
        for (int i = 0; i < 2; i++) {   // X: 32 rows x 16 chunks
            int idx = tid + 256 * i, r = idx >> 4, ch = idx & 15;
            cpa16(base + FB_XH + r * 272 + ch * 16,
                  Xh + (size_t)(c * 32 + r) * NPIX + nb + ch * 8);
        }
#pragma unroll
        for (int i = 0; i < 2; i++) {   // W: 128 rows x 4 chunks
            int idx = tid + 256 * i, m = idx >> 2, ch = idx & 3;
            cpa16(base + FB_WH + m * 80 + ch * 16,
                  Wh + (size_t)m * 256 + c * 32 + ch * 8);
        }
    };

    fill(0, 0); CP_COMMIT();
    fill(1, 1); CP_COMMIT();

    const int lr = lane & 7, g = lane >> 3;
    const int fr = lr + ((g & 1) << 3), fc = g >> 1;
    const int wm = w >> 2, wn = w & 3;

    float C[4][4][4];
#pragma unroll
    for (int i = 0; i < 4; i++)
#pragma unroll
        for (int j = 0; j < 4; j++)
#pragma unroll
            for (int k = 0; k < 4; k++) C[i][j][k] = 0.f;

    for (int c = 0; c < 8; c++) {
        if (c < 6) { CP_WAIT(1); } else { CP_WAIT(0); }
        __syncthreads();
        const uint32_t base = sb + (c & 1) * FB_BUF;
#pragma unroll
        for (int kt = 0; kt < 2; kt++) {
            uint32_t bh[2][4];
#pragma unroll
            for (int nh = 0; nh < 2; nh++)
                ldsm4t(bh[nh], base + FB_XH + (kt * 16 + fr) * 272 +
                               (wn * 32 + nh * 16 + fc * 8) * 2);
#pragma unroll
            for (int mt = 0; mt < 4; mt++) {
                uint32_t ah[4];
                ldsm4(ah, base + FB_WH + (wm * 64 + mt * 16 + fr) * 80 +
                          (kt * 16 + fc * 8) * 2);
#pragma unroll
                for (int nh = 0; nh < 2; nh++) {
                    mma_f16(C[mt][2 * nh], ah, bh[nh][0], bh[nh][1]);
                    mma_f16(C[mt][2 * nh + 1], ah, bh[nh][2], bh[nh][3]);
                }
            }
        }
        __syncthreads();
        if (c + 2 < 8) { fill(c + 2, c & 1); CP_COMMIT(); }
    }

    // epilogue: bias+scale, fp16, stage to target layout (pitch 272B)
    __half* stage = (__half*)sm;
#pragma unroll
    for (int mt = 0; mt < 4; mt++) {
        int m0 = wm * 64 + mt * 16 + (lane >> 2);
        float b0 = bias[m0], b1 = bias[m0 + 8];
#pragma unroll
        for (int nt = 0; nt < 4; nt++) {
            int n = wn * 32 + nt * 8 + 2 * (lane & 3);
            float v0 = (C[mt][nt][0] + b0) * scale;
            float v1 = (C[mt][nt][1] + b0) * scale;
            float v2 = (C[mt][nt][2] + b1) * scale;
            float v3 = (C[mt][nt][3] + b1) * scale;
            if (vmode == 0) {   // stage [n][d]
                stage[n * 136 + m0] = __float2half_rn(v0);
                stage[(n + 1) * 136 + m0] = __float2half_rn(v1);
                stage[n * 136 + m0 + 8] = __float2half_rn(v2);
                stage[(n + 1) * 136 + m0 + 8] = __float2half_rn(v3);
            } else {            // stage [d][n]
                *(uint32_t*)&stage[m0 * 136 + n] = pkh(v0, v1);
                *(uint32_t*)&stage[(m0 + 8) * 136 + n] = pkh(v2, v3);
            }
        }
    }
    __syncthreads();
#pragma unroll
    for (int i = 0; i < 8; i++) {
        int idx = tid + 256 * i, r = idx >> 4, ch = idx & 15;
        uint4 v = *(uint4*)((char*)sm + r * 272 + ch * 16);
        if (vmode == 0)
            *(uint4*)(out + (size_t)(nb + r) * DEMB + ch * 8) = v;
        else
            *(uint4*)(out + (size_t)r * NPIX + nb + ch * 8) = v;
    }
}

// ---------------- final GEMM (1-term fp16): out = relu(BN(Wp @ comb)) -------
#define FINAL_SMEM 67584    // epilogue stage (128 rows x 528B) dominates

__global__ __launch_bounds__(256, 2) void final_mma(
    float* __restrict__ Y,
    const float* __restrict__ bng, const float* __restrict__ bnb,
    const float* __restrict__ bnm, const float* __restrict__ bnv)
{
    extern __shared__ char sm[];
    const int tid = threadIdx.x, lane = tid & 31, w = tid >> 5;
    const int nb = blockIdx.x * 128;
    const int mbase = blockIdx.y * 128;
    const int b = blockIdx.z;

    const __half* Xh = g_ch + (size_t)b * 256 * NPIX;
    const __half* Wh = g_w + 196608;
    float* Yb = Y + (size_t)b * 256 * NPIX;

    const uint32_t sb = smem_u32(sm);

    auto fill = [&](int c, int s) {
        uint32_t base = sb + s * FB_BUF;
#pragma unroll
        for (int i = 0; i < 2; i++) {
            int idx = tid + 256 * i, r = idx >> 4, ch = idx & 15;
            cpa16(base + FB_XH + r * 272 + ch * 16,
                  Xh + (size_t)(c * 32 + r) * NPIX + nb + ch * 8);
        }
#pragma unroll
        for (int i = 0; i < 2; i++) {
            int idx = tid + 256 * i, m = idx >> 2, ch = idx & 3;
            cpa16(base + FB_WH + m * 80 + ch * 16,
                  Wh + (size_t)(mbase + m) * 256 + c * 32 + ch * 8);
        }
    };

    fill(0, 0); CP_COMMIT();
    fill(1, 1); CP_COMMIT();

    const int lr = lane & 7, g = lane >> 3;
    const int fr = lr + ((g & 1) << 3), fc = g >> 1;
    const int wm = w >> 2, wn = w & 3;

    float C[4][4][4];
#pragma unroll
    for (int i = 0; i < 4; i++)
#pragma unroll
        for (int j = 0; j < 4; j++)
#pragma unroll
            for (int k = 0; k < 4; k++) C[i][j][k] = 0.f;

    for (int c = 0; c < 8; c++) {
        if (c < 6) { CP_WAIT(1); } else { CP_WAIT(0); }
        __syncthreads();
        const uint32_t base = sb + (c & 1) * FB_BUF;
#pragma unroll
        for (int kt = 0; kt < 2; kt++) {
            uint32_t bh[2][4];
#pragma unroll
            for (int nh = 0; nh < 2; nh++)
                ldsm4t(bh[nh], base + FB_XH + (kt * 16 + fr) * 272 +
                               (wn * 32 + nh * 16 + fc * 8) * 2);
#pragma unroll
            for (int mt = 0; mt < 4; mt++) {
                uint32_t ah[4];
                ldsm4(ah, base + FB_WH + (wm * 64 + mt * 16 + fr) * 80 +
                          (kt * 16 + fc * 8) * 2);
#pragma unroll
                for (int nh = 0; nh < 2; nh++) {
                    mma_f16(C[mt][2 * nh], ah, bh[nh][0], bh[nh][1]);
                    mma_f16(C[mt][2 * nh + 1], ah, bh[nh][2], bh[nh][3]);
                }
            }
        }
        __syncthreads();
        if (c + 2 < 8) { fill(c + 2, c & 1); CP_COMMIT(); }
    }

    // BN + ReLU, stage fp32 [m][n] pitch 132 floats, coalesced STG
    float* stage = (float*)sm;
#pragma unroll
    for (int mt = 0; mt < 4; mt++) {
        int ml = wm * 64 + mt * 16 + (lane >> 2);
        int m0 = mbase + ml, m1 = m0 + 8;
        float i0 = bng[m0] * rsqrtf(bnv[m0] + BN_EPS);
        float s0 = bnb[m0] - bnm[m0] * i0;
        float i1 = bng[m1] * rsqrtf(bnv[m1] + BN_EPS);
        float s1 = bnb[m1] - bnm[m1] * i1;
#pragma unroll
        for (int nt = 0; nt < 4; nt++) {
            int n = wn * 32 + nt * 8 + 2 * (lane & 3);
            stage[ml * 132 + n]       = fmaxf(fmaf(C[mt][nt][0], i0, s0), 0.f);
            stage[ml * 132 + n + 1]   = fmaxf(fmaf(C[mt][nt][1], i0, s0), 0.f);
            stage[(ml + 8) * 132 + n]     = fmaxf(fmaf(C[mt][nt][2], i1, s1), 0.f);
            stage[(ml + 8) * 132 + n + 1] = fmaxf(fmaf(C[mt][nt][3], i1, s1), 0.f);
        }
    }
    __syncthreads();
#pragma unroll
    for (int i = 0; i < 16; i++) {
        int idx = tid + 256 * i, r = idx >> 5, ch = idx & 31;
        float4 v = *(float4*)((char*)sm + r * 528 + ch * 16);
        *(float4*)&Yb[(size_t)(mbase + r) * NPIX + nb + ch * 4] = v;
    }
}

// ---------------- flash attention: BQ=64, BK=128 (champion config) ----------
// warps: slab = w&3 (16-q slab), khalf = w>>2 (64-key half of each 128-key tile)
// smem: Q 16KB | K0 K1 V0 V1 32KB each = 144KB; 1 CTA/SM, grid 1024 (~7 waves)
#define ATT_SMEM (16384 + 4 * 32768)

__global__ __launch_bounds__(256, 1) void attn_kernel()
{
    extern __shared__ char sm[];
    const int tid = threadIdx.x, lane = tid & 31, w = tid >> 5;
    const int slab = w & 3, khalf = w >> 2;
    const int qt = blockIdx.x, dir = blockIdx.y, b = blockIdx.z;
    const int qbase = qt * 64;
    const size_t PLANE = (size_t)DEMB * NPIX;

    const __half* Qg = g_h + ((size_t)(dir * 3 + 0) * NBATCH + b) * PLANE;
    const __half* Kg = g_h + ((size_t)(dir * 3 + 1) * NBATCH + b) * PLANE;
    const __half* Vg = g_h + ((size_t)(dir * 3 + 2) * NBATCH + b) * PLANE;
    __half* Oh = g_ch + ((size_t)b * 256 + dir * 128) * NPIX;

    const uint32_t bQ = smem_u32(sm);
    const uint32_t bK0 = bQ + 16384, bK1 = bQ + 49152;
    const uint32_t bV0 = bQ + 81920, bV1 = bQ + 114688;

    auto fillA = [&](uint32_t dst, const __half* src, int rstride) {
#pragma unroll
        for (int i = 0; i < 8; i++) {
            int idx = tid + 256 * i;
            int r = idx >> 4, c = idx & 15;
            int ch = (c & 8) | ((c & 7) ^ (r & 7));
            cpa16(dst + r * 256 + ch * 16, src + (size_t)r * rstride + c * 8);
        }
    };
    auto fillQ = [&]() {
#pragma unroll
        for (int i = 0; i < 4; i++) {
            int idx = tid + 256 * i;
            int r = idx >> 4, c = idx & 15;
            int ch = (c & 8) | ((c & 7) ^ (r & 7));
            cpa16(bQ + r * 256 + ch * 16, Qg + (size_t)(qbase + r) * DEMB + c * 8);
        }
    };

    fillQ();                                              CP_COMMIT();
    fillA(bK0, Kg, DEMB); fillA(bV0, Vg, NPIX);           CP_COMMIT();
    fillA(bK1, Kg + (size_t)128 * DEMB, DEMB);
    fillA(bV1, Vg + 128, NPIX);                           CP_COMMIT();

    const int lr = lane & 7, g = lane >> 3;
    const int a_row = lr + ((g & 1) << 3), a_ch = g >> 1;
    const int b_row = lr + ((g >> 1) << 3), b_ch = g & 1;
    const int q0 = 16 * slab;

    CP_WAIT(2);
    __syncthreads();

    uint32_t qf[8][4];
#pragma unroll
    for (int k = 0; k < 8; k++) {
        int ch = 2 * k + a_ch;
        ldsm4(qf[k], bQ + (q0 + a_row) * 256 + (((ch & 8) | ((ch & 7) ^ lr)) << 4));
    }

    float O[16][4];
#pragma unroll
    for (int i = 0; i < 16; i++)
#pragma unroll
        for (int j = 0; j < 4; j++) O[i][j] = 0.f;
    float l0 = 0.f, l1 = 0.f;

    for (int t = 0; t < 32; t++) {
        if (t < 30) { CP_WAIT(1); } else { CP_WAIT(0); }
        __syncthreads();
        const uint32_t bK = (t & 1) ? bK1 : bK0;
        const uint32_t bV = (t & 1) ? bV1 : bV0;

        // ---- S (16q x 64 keys of this half): d-outer, kc-inner -> 8 chains --
        float S[8][4];
#pragma unroll
        for (int i = 0; i < 8; i++)
#pragma unroll
            for (int j = 0; j < 4; j++) S[i][j] = 0.f;
#pragma unroll
        for (int d = 0; d < 8; d++) {
            int ch = 2 * d + b_ch;
            uint32_t co = ((ch & 8) | ((ch & 7) ^ lr)) << 4;
#pragma unroll
            for (int kc = 0; kc < 4; kc++) {
                uint32_t bk[4];
                ldsm4(bk, bK + ((khalf * 4 + kc) * 16 + b_row) * 256 + co);
                mma_f16(S[2 * kc], qf[d], bk[0], bk[1]);
                mma_f16(S[2 * kc + 1], qf[d], bk[2], bk[3]);
            }
        }

        // ---- softmax: raw MUFU ex2 (Q pre-scaled by log2e) ----
        uint32_t ph[4][4];
#pragma unroll
        for (int kc = 0; kc < 4; kc++) {
            float* s0 = S[2 * kc];
            float* s1 = S[2 * kc + 1];
            float e00 = ex2(s0[0]), e01 = ex2(s0[1]);
            float e02 = ex2(s0[2]), e03 = ex2(s0[3]);
            float e10 = ex2(s1[0]), e11 = ex2(s1[1]);
            float e12 = ex2(s1[2]), e13 = ex2(s1[3]);
            l0 += e00 + e01 + e10 + e11;
            l1 += e02 + e03 + e12 + e13;
            ph[kc][0] = pkh(e00, e01); ph[kc][1] = pkh(e02, e03);
            ph[kc][2] = pkh(e10, e11); ph[kc][3] = pkh(e12, e13);
        }

        // ---- O += P V over this key half: kc-outer, nb-inner (16 chains) ----
#pragma unroll
        for (int kc = 0; kc < 4; kc++) {
            int ch = 2 * (khalf * 4 + kc) + b_ch;
            uint32_t co = ((ch & 8) | ((ch & 7) ^ lr)) << 4;
#pragma unroll
            for (int nb2 = 0; nb2 < 8; nb2++) {
                uint32_t bv[4];
                ldsm4(bv, bV + (nb2 * 16 + b_row) * 256 + co);
                mma_f16(O[2 * nb2], ph[kc], bv[0], bv[1]);
                mma_f16(O[2 * nb2 + 1], ph[kc], bv[2], bv[3]);
            }
        }
        __syncthreads();
        if (t + 2 < 32) {
            fillA((t & 1) ? bK1 : bK0, Kg + (size_t)(t + 2) * 128 * DEMB, DEMB);
            fillA((t & 1) ? bV1 : bV0, Vg + (t + 2) * 128, NPIX);
            CP_COMMIT();
        }
    }

    // quad-reduce l over the 16-key column groups this warp saw
#pragma unroll
    for (int off = 1; off < 4; off <<= 1) {
        l0 += __shfl_xor_sync(0xffffffffu, l0, off);
        l1 += __shfl_xor_sync(0xffffffffu, l1, off);
    }

    // cross-warp (key-half) reduce through smem, then store
    float* sO = (float*)(sm + 16384);          // 64 rows x pitch 132 fp32
    float* sL = (float*)(sm + 16384 + 34048);  // 64 floats
    const int row0 = slab * 16 + (lane >> 2);
    __syncthreads();
    if (khalf == 1) {
        if ((lane & 3) == 0) { sL[row0] = l0; sL[row0 + 8] = l1; }
#pragma unroll
        for (int nb2 = 0; nb2 < 16; nb2++) {
            int d = nb2 * 8 + 2 * (lane & 3);
            sO[row0 * 132 + d] = O[nb2][0];
            sO[row0 * 132 + d + 1] = O[nb2][1];
            sO[(row0 + 8) * 132 + d] = O[nb2][2];
            sO[(row0 + 8) * 132 + d + 1] = O[nb2][3];
        }
    }
    __syncthreads();
    if (khalf == 0) {
        l0 += sL[row0];
        l1 += sL[row0 + 8];
        const float inv0 = 1.f / l0, inv1 = 1.f / l1;
        const int qg0 = qbase + row0;
#pragma unroll
        for (int nb2 = 0; nb2 < 16; nb2++) {
            int d = nb2 * 8 + 2 * (lane & 3);
            float v0 = (O[nb2][0] + sO[row0 * 132 + d]) * inv0;
            float v1 = (O[nb2][1] + sO[row0 * 132 + d + 1]) * inv0;
            float v2 = (O[nb2][2] + sO[(row0 + 8) * 132 + d]) * inv1;
            float v3 = (O[nb2][3] + sO[(row0 + 8) * 132 + d + 1]) * inv1;
            Oh[(size_t)d * NPIX + qg0]           = __float2half_rn(v0);
            Oh[(size_t)(d + 1) * NPIX + qg0]     = __float2half_rn(v1);
            Oh[(size_t)d * NPIX + qg0 + 8]       = __float2half_rn(v2);
            Oh[(size_t)(d + 1) * NPIX + qg0 + 8] = __float2half_rn(v3);
        }
    }
}

// ---------------- launch -----------------------------------------------------
extern "C" void kernel_launch(void* const* d_in, const int* in_sizes, int n_in,
                              void* d_out, int out_size)
{
    (void)in_sizes; (void)n_in; (void)out_size;
    const float* f_rgb   = (const float*)d_in[0];
    const float* f_pl    = (const float*)d_in[1];
    const float* w_q_rgb = (const float*)d_in[2];
    const float* b_q_rgb = (const float*)d_in[3];
    const float* w_k_pl  = (const float*)d_in[4];
    const float* b_k_pl  = (const float*)d_in[5];
    const float* w_v_pl  = (const float*)d_in[6];
    const float* b_v_pl  = (const float*)d_in[7];
    const float* w_q_pl  = (const float*)d_in[8];
    const float* b_q_pl  = (const float*)d_in[9];
    const float* w_k_rgb = (const float*)d_in[10];
    const float* b_k_rgb = (const float*)d_in[11];
    const float* w_v_rgb = (const float*)d_in[12];
    const float* b_v_rgb = (const float*)d_in[13];
    const float* w_proj  = (const float*)d_in[14];
    const float* bn_g    = (const float*)d_in[15];
    const float* bn_b    = (const float*)d_in[16];
    const float* bn_m    = (const float*)d_in[17];
    const float* bn_v    = (const float*)d_in[18];

    __half *hp, *xp, *wp;
    cudaGetSymbolAddress((void**)&hp, g_h);
    cudaGetSymbolAddress((void**)&xp, g_x);
    cudaGetSymbolAddress((void**)&wp, g_w);

    const int NX = NBATCH * 256 * NPIX;
    CvtTab ct;
    const float* srcs[9] = { f_rgb, f_pl, w_q_rgb, w_k_rgb, w_v_rgb,
                             w_k_pl, w_v_pl, w_q_pl, w_proj };
    int sizes[9] = { NX, NX, 32768, 32768, 32768, 32768, 32768, 32768, 65536 };
    __half* dsts[9] = { xp, xp + NX, wp, wp + 32768, wp + 65536,
                        wp + 98304, wp + 131072, wp + 163840, wp + 196608 };
    int off = 0;
    for (int i = 0; i < 9; i++) {
        ct.src[i] = srcs[i]; ct.dst[i] = dsts[i];
        ct.blkoff[i] = off;
        off += sizes[i] / 2048;
    }
    ct.blkoff[9] = off;
    cvt_all<<<off, 256>>>(ct);

    const size_t PL = (size_t)NBATCH * DEMB * NPIX;
    ProjTab pt;
    int woffs[6] = { 0, 32768, 65536, 98304, 131072, 163840 };
    const float* biases[6] = { b_q_rgb, b_k_rgb, b_v_rgb, b_k_pl, b_v_pl, b_q_pl };
    float scales[6] = { ATT_SCALE * LOG2E, 1.f, 1.f, 1.f, 1.f, ATT_SCALE * LOG2E };
    int vmodes[6] = { 0, 0, 1, 0, 1, 0 };
    int planes[6] = { 0, 4, 5, 1, 2, 3 };  // Qa, Kb, Vb, Ka, Va, Qb
    for (int i = 0; i < 6; i++) {
        pt.woff[i] = woffs[i]; pt.bias[i] = biases[i];
        pt.scale[i] = scales[i]; pt.vmode[i] = vmodes[i];
        pt.out[i] = hp + (size_t)planes[i] * PL;
    }

    cudaFuncSetAttribute(proj_mma, cudaFuncAttributeMaxDynamicSharedMemorySize, GEMM_SMEM);
    proj_mma<<<dim3(32, 3, 16), 256, GEMM_SMEM>>>(pt);

    cudaFuncSetAttribute(attn_kernel, cudaFuncAttributeMaxDynamicSharedMemorySize, ATT_SMEM);
    attn_kernel<<<dim3(NPIX / 64, 2, NBATCH), 256, ATT_SMEM>>>();

    cudaFuncSetAttribute(final_mma, cudaFuncAttributeMaxDynamicSharedMemorySize, FINAL_SMEM);
    final_mma<<<dim3(32, 2, NBATCH), 256, FINAL_SMEM>>>((float*)d_out,
                                                        bn_g, bn_b, bn_m, bn_v);
}